// round 14
// baseline (speedup 1.0000x reference)
#include <cuda_runtime.h>
#include <math.h>

#define BB 16
#define NN 256
#define HID 128
#define NHEAD 8
#define HD 16
#define ROWS (BB*NN)   // 4096
#define NBH (BB*NHEAD) // 128
#define NRQ (NBH*NN)   // 32768 (bh, query) pairs
#define NSEG 4         // key-split segments
#define SEGK (NN/NSEG) // 64 keys per segment

// ---------------- scratch (device globals; no allocation allowed) ----------
__device__ float g_h[ROWS*HID];        // layer input / output h
__device__ float g_qkv[ROWS*3*HID];    // qkv
__device__ float g_y[ROWS*HID];        // attention output
__device__ float g_mlp[ROWS*4*HID];    // MLP hidden; also attn partial acc (4*NRQ*HD fits exactly)
__device__ float g_pm[NSEG*NRQ];       // attn partial max
__device__ float g_ps[NSEG*NRQ];       // attn partial sum
__device__ float g_c1[3*NHEAD];
__device__ float g_c2[3*NHEAD];

__device__ __forceinline__ float* bufptr(int id) {
    switch (id) {
        case 0: return g_h;
        case 2: return g_qkv;
        case 3: return g_y;
        default: return g_mlp;
    }
}

// ---------------- edge coefficient precompute ------------------------------
__global__ void k_coef(const float* __restrict__ We_in, const float* __restrict__ We) {
    int t = threadIdx.x;
    if (t >= 48) return;
    int l = t / 16, c = t % 16;
    float s = 0.f;
    for (int d = 0; d < HID; d++) s += We_in[d] * We[(l*HID + d)*16 + c];
    if (c < NHEAD) g_c1[l*NHEAD + c] = s;
    else           g_c2[l*NHEAD + (c - NHEAD)] = s;
}

// ---------------- node embedding: h = nf @ Wn (K=2), float4 ----------------
__global__ void k_embed(const float* __restrict__ nf, const float* __restrict__ Wn) {
    int i = blockIdx.x * blockDim.x + threadIdx.x;   // one float4 per thread
    int r = i >> 5, c4 = (i & 31) * 4;
    float a = nf[r*2], b = nf[r*2+1];
    float4 w0 = *reinterpret_cast<const float4*>(&Wn[c4]);
    float4 w1 = *reinterpret_cast<const float4*>(&Wn[HID + c4]);
    float4 o;
    o.x = a*w0.x + b*w1.x; o.y = a*w0.y + b*w1.y;
    o.z = a*w0.z + b*w1.z; o.w = a*w0.w + b*w1.w;
    *reinterpret_cast<float4*>(&g_h[r*HID + c4]) = o;
}

// ---------------- fused LN + GEMM (K = HID = 128 only) ---------------------
// C[128 x 64 tile] = LN(X [+ R]) @ W.   RELU optionally applied.
#define AS_STRIDE 132
#define LNG_SMEM ((128*AS_STRIDE + 128*64) * 4)

template<int RES, int RELU>
__global__ __launch_bounds__(256)
void k_lngemm(int xid, int resid, const float* __restrict__ Bm, int cid, int Nc,
              const float* __restrict__ gam, const float* __restrict__ bet) {
    extern __shared__ float sm[];
    float* As = sm;                    // [128][AS_STRIDE]
    float* Bs = sm + 128*AS_STRIDE;    // [128][64]
    const float* X = bufptr(xid);
    const float* Rp = RES ? bufptr(resid) : nullptr;
    float* C = bufptr(cid);
    int tid = threadIdx.x, lane = tid & 31, warp = tid >> 5;
    int rowBase = blockIdx.y * 128, colBase = blockIdx.x * 64;

    // ---- stage B panel: 128 x 64, coalesced ----
    #pragma unroll
    for (int i = 0; i < 8; i++) {
        int f4 = i*256 + tid;
        int kk = f4 >> 4, n = (f4 & 15) * 4;
        *reinterpret_cast<float4*>(&Bs[kk*64 + n]) =
            *reinterpret_cast<const float4*>(&Bm[(size_t)kk*Nc + colBase + n]);
    }

    // ---- stage A panel with fused layernorm: one warp per row ----
    float4 gv = *reinterpret_cast<const float4*>(&gam[lane*4]);
    float4 bv = *reinterpret_cast<const float4*>(&bet[lane*4]);
    #pragma unroll
    for (int i = 0; i < 16; i++) {
        int r = i*8 + warp;
        float4 v = *reinterpret_cast<const float4*>(
            &X[(size_t)(rowBase + r)*HID + lane*4]);
        if (RES) {
            float4 rv = *reinterpret_cast<const float4*>(
                &Rp[(size_t)(rowBase + r)*HID + lane*4]);
            v.x += rv.x; v.y += rv.y; v.z += rv.z; v.w += rv.w;
        }
        float s = v.x + v.y + v.z + v.w;
        #pragma unroll
        for (int o = 16; o > 0; o >>= 1) s += __shfl_xor_sync(0xffffffffu, s, o);
        float mean = s * (1.0f/HID);
        float dx = v.x-mean, dy = v.y-mean, dz = v.z-mean, dw = v.w-mean;
        float s2 = dx*dx + dy*dy + dz*dz + dw*dw;
        #pragma unroll
        for (int o = 16; o > 0; o >>= 1) s2 += __shfl_xor_sync(0xffffffffu, s2, o);
        float rstd = rsqrtf(s2 * (1.0f/HID) + 1e-5f);
        float4 o4;
        o4.x = dx*rstd*gv.x + bv.x; o4.y = dy*rstd*gv.y + bv.y;
        o4.z = dz*rstd*gv.z + bv.z; o4.w = dw*rstd*gv.w + bv.w;
        *reinterpret_cast<float4*>(&As[r*AS_STRIDE + lane*4]) = o4;
    }
    __syncthreads();

    // ---- compute: per-thread 8x4, K=128, no further barriers ----
    int tx = tid & 15, ty = tid >> 4;
    float acc[8][4] = {};
    #pragma unroll 4
    for (int k4 = 0; k4 < 32; k4++) {
        float4 b4[4];
        #pragma unroll
        for (int dk = 0; dk < 4; dk++)
            b4[dk] = *reinterpret_cast<float4*>(&Bs[(k4*4 + dk)*64 + tx*4]);
        #pragma unroll
        for (int r = 0; r < 8; r++) {
            float4 a4 = *reinterpret_cast<float4*>(&As[(ty*8 + r)*AS_STRIDE + k4*4]);
            acc[r][0] += a4.x*b4[0].x; acc[r][1] += a4.x*b4[0].y;
            acc[r][2] += a4.x*b4[0].z; acc[r][3] += a4.x*b4[0].w;
            acc[r][0] += a4.y*b4[1].x; acc[r][1] += a4.y*b4[1].y;
            acc[r][2] += a4.y*b4[1].z; acc[r][3] += a4.y*b4[1].w;
            acc[r][0] += a4.z*b4[2].x; acc[r][1] += a4.z*b4[2].y;
            acc[r][2] += a4.z*b4[2].z; acc[r][3] += a4.z*b4[2].w;
            acc[r][0] += a4.w*b4[3].x; acc[r][1] += a4.w*b4[3].y;
            acc[r][2] += a4.w*b4[3].z; acc[r][3] += a4.w*b4[3].w;
        }
    }
    #pragma unroll
    for (int r = 0; r < 8; r++) {
        int row = rowBase + ty*8 + r;
        int col = colBase + tx*4;
        float4 v = {acc[r][0], acc[r][1], acc[r][2], acc[r][3]};
        if (RELU) {
            v.x = fmaxf(v.x, 0.f); v.y = fmaxf(v.y, 0.f);
            v.z = fmaxf(v.z, 0.f); v.w = fmaxf(v.w, 0.f);
        }
        *reinterpret_cast<float4*>(&C[(size_t)row*Nc + col]) = v;
    }
}

// ---------------- fp32 GEMM (K=512): C = A @ W + residual, kc=32 -----------
__global__ __launch_bounds__(256)
void k_gemm2(int aid, const float* __restrict__ Bm,
             int resid, int cid, int K, int Nc) {
    __shared__ float As[32][64];
    __shared__ float Bs[32][64];
    const float* A = bufptr(aid);
    float* C = bufptr(cid);
    int tid = threadIdx.x;
    int tx = tid & 15, ty = tid >> 4;
    int rowBase = blockIdx.y * 64;
    int colBase = blockIdx.x * 64;
    float acc[4][4] = {};
    for (int k0 = 0; k0 < K; k0 += 32) {
        #pragma unroll
        for (int q = 0; q < 2; q++) {      // A tile 64m x 32k, transposed store
            int fidx = tid*2 + q;
            int m = fidx >> 3, kk = (fidx & 7) * 4;
            float4 a4 = *reinterpret_cast<const float4*>(&A[(size_t)(rowBase+m)*K + k0 + kk]);
            As[kk+0][m] = a4.x; As[kk+1][m] = a4.y; As[kk+2][m] = a4.z; As[kk+3][m] = a4.w;
        }
        #pragma unroll
        for (int q = 0; q < 2; q++) {      // B tile 32k x 64n, coalesced
            int f4 = q*256 + tid;
            int kk = f4 >> 4, n = (f4 & 15) * 4;
            *reinterpret_cast<float4*>(&Bs[kk][n]) =
                *reinterpret_cast<const float4*>(&Bm[(size_t)(k0+kk)*Nc + colBase + n]);
        }
        __syncthreads();
        #pragma unroll
        for (int kk = 0; kk < 32; kk++) {
            float4 b4 = *reinterpret_cast<float4*>(&Bs[kk][tx*4]);
            float4 a4 = *reinterpret_cast<float4*>(&As[kk][ty*4]);
            float av[4] = {a4.x, a4.y, a4.z, a4.w};
            float bvv[4] = {b4.x, b4.y, b4.z, b4.w};
            #pragma unroll
            for (int i = 0; i < 4; i++)
                #pragma unroll
                for (int j = 0; j < 4; j++)
                    acc[i][j] += av[i] * bvv[j];
        }
        __syncthreads();
    }
    const float* R = bufptr(resid);
    #pragma unroll
    for (int i = 0; i < 4; i++) {
        int row = rowBase + ty*4 + i;
        int col = colBase + tx*4;
        float4 v = {acc[i][0], acc[i][1], acc[i][2], acc[i][3]};
        float4 rv = *reinterpret_cast<const float4*>(&R[(size_t)row*HID + col]);
        v.x += rv.x; v.y += rv.y; v.z += rv.z; v.w += rv.w;
        *reinterpret_cast<float4*>(&C[(size_t)row*Nc + col]) = v;
    }
}

// ---------------- attention, split-KV x4, 2 queries per thread -------------
// Block = (bh, seg); 128 threads; thread t handles queries t and t+128
// over keys [seg*64, seg*64+64). Writes unnormalized softmax partials.
__global__ __launch_bounds__(128)
void k_attn(const float* __restrict__ edge, int layer) {
    int blk = blockIdx.x;              // 0..511
    int bh = blk & (NBH-1), sg = blk >> 7;
    int b = bh >> 3, h = bh & 7;
    __shared__ float ks[SEGK][HD];
    __shared__ float vs[SEGK][HD];
    int tid = threadIdx.x;             // 0..127
    int j0 = sg * SEGK;

    {   // cooperative K/V stage: 64 rows x 4 float4-parts = 256 f4, 2 per thread
        #pragma unroll
        for (int i = 0; i < 2; i++) {
            int idx = i*128 + tid;
            int rr = idx >> 2, part = idx & 3;
            const float* base = &g_qkv[(size_t)(b*NN + j0 + rr)*384 + h*HD];
            *reinterpret_cast<float4*>(&ks[rr][part*4]) =
                *reinterpret_cast<const float4*>(base + HID   + part*4);
            *reinterpret_cast<float4*>(&vs[rr][part*4]) =
                *reinterpret_cast<const float4*>(base + 2*HID + part*4);
        }
    }
    __syncthreads();

    float q0[HD], q1[HD];
    {
        const float* qp0 = &g_qkv[(size_t)(b*NN + tid)*384 + h*HD];
        const float* qp1 = &g_qkv[(size_t)(b*NN + tid + 128)*384 + h*HD];
        #pragma unroll
        for (int d4 = 0; d4 < 4; d4++) {
            float4 a = *reinterpret_cast<const float4*>(qp0 + d4*4);
            float4 c = *reinterpret_cast<const float4*>(qp1 + d4*4);
            q0[d4*4+0] = a.x*0.25f; q0[d4*4+1] = a.y*0.25f;
            q0[d4*4+2] = a.z*0.25f; q0[d4*4+3] = a.w*0.25f;
            q1[d4*4+0] = c.x*0.25f; q1[d4*4+1] = c.y*0.25f;
            q1[d4*4+2] = c.z*0.25f; q1[d4*4+3] = c.w*0.25f;
        }
    }

    float cb = g_c1[layer*NHEAD + h];
    float cg = g_c2[layer*NHEAD + h];
    const float4* er0 = reinterpret_cast<const float4*>(edge + (size_t)(b*NN + tid)*NN);
    const float4* er1 = reinterpret_cast<const float4*>(edge + (size_t)(b*NN + tid + 128)*NN);

    float mx0 = -1e30f, sum0 = 0.f;
    float mx1 = -1e30f, sum1 = 0.f;
    float acc0[HD] = {}, acc1[HD] = {};

    #pragma unroll 2
    for (int j4 = 0; j4 < SEGK/4; j4++) {           // 16 iterations
        float4 e40 = __ldg(&er0[sg*(SEGK/4) + j4]);
        float4 e41 = __ldg(&er1[sg*(SEGK/4) + j4]);
        float ej0s[4] = {e40.x, e40.y, e40.z, e40.w};
        float ej1s[4] = {e41.x, e41.y, e41.z, e41.w};
        #pragma unroll
        for (int jj = 0; jj < 4; jj++) {
            int j = j4*4 + jj;                      // local key index
            float4 k4[4];
            #pragma unroll
            for (int d4 = 0; d4 < 4; d4++)
                k4[d4] = *reinterpret_cast<float4*>(&ks[j][d4*4]);
            float s0 = 0.f, s1 = 0.f;
            #pragma unroll
            for (int d4 = 0; d4 < 4; d4++) {
                s0 += q0[d4*4+0]*k4[d4].x + q0[d4*4+1]*k4[d4].y
                    + q0[d4*4+2]*k4[d4].z + q0[d4*4+3]*k4[d4].w;
                s1 += q1[d4*4+0]*k4[d4].x + q1[d4*4+1]*k4[d4].y
                    + q1[d4*4+2]*k4[d4].z + q1[d4*4+3]*k4[d4].w;
            }
            float ej0 = ej0s[jj], ej1 = ej1s[jj];
            s0 += ej0 * cb;
            s1 += ej1 * cb;
            if (s0 > mx0) {
                float sc = __expf(mx0 - s0);
                mx0 = s0; sum0 *= sc;
                #pragma unroll
                for (int d = 0; d < HD; d++) acc0[d] *= sc;
            }
            if (s1 > mx1) {
                float sc = __expf(mx1 - s1);
                mx1 = s1; sum1 *= sc;
                #pragma unroll
                for (int d = 0; d < HD; d++) acc1[d] *= sc;
            }
            float p0 = __expf(s0 - mx0);
            float p1 = __expf(s1 - mx1);
            sum0 += p0; sum1 += p1;
            float w0 = p0 * ej0 * cg;
            float w1 = p1 * ej1 * cg;
            #pragma unroll
            for (int d4 = 0; d4 < 4; d4++) {
                float4 v4 = *reinterpret_cast<float4*>(&vs[j][d4*4]);
                acc0[d4*4+0] += w0*v4.x; acc0[d4*4+1] += w0*v4.y;
                acc0[d4*4+2] += w0*v4.z; acc0[d4*4+3] += w0*v4.w;
                acc1[d4*4+0] += w1*v4.x; acc1[d4*4+1] += w1*v4.y;
                acc1[d4*4+2] += w1*v4.z; acc1[d4*4+3] += w1*v4.w;
            }
        }
    }
    // write partials (unnormalized)
    int rq0 = bh*NN + tid;
    int rq1 = bh*NN + tid + 128;
    g_pm[sg*NRQ + rq0] = mx0;  g_ps[sg*NRQ + rq0] = sum0;
    g_pm[sg*NRQ + rq1] = mx1;  g_ps[sg*NRQ + rq1] = sum1;
    float* pa0 = &g_mlp[(size_t)(sg*NRQ + rq0)*HD];
    float* pa1 = &g_mlp[(size_t)(sg*NRQ + rq1)*HD];
    #pragma unroll
    for (int d4 = 0; d4 < 4; d4++) {
        float4 o0 = {acc0[d4*4+0], acc0[d4*4+1], acc0[d4*4+2], acc0[d4*4+3]};
        float4 o1 = {acc1[d4*4+0], acc1[d4*4+1], acc1[d4*4+2], acc1[d4*4+3]};
        *reinterpret_cast<float4*>(pa0 + d4*4) = o0;
        *reinterpret_cast<float4*>(pa1 + d4*4) = o1;
    }
}

// ---------------- attention combine: merge 4 split-KV partials -------------
__global__ __launch_bounds__(256)
void k_attn_comb() {
    int gid = blockIdx.x * 256 + threadIdx.x;   // NRQ*4 = 131072 threads
    int rq = gid >> 2, d4 = gid & 3;
    int bh = rq >> 8, qi = rq & 255;
    int b = bh >> 3, h = bh & 7;
    float m0 = g_pm[rq],         m1 = g_pm[NRQ + rq];
    float m2 = g_pm[2*NRQ + rq], m3 = g_pm[3*NRQ + rq];
    float m = fmaxf(fmaxf(m0, m1), fmaxf(m2, m3));
    float w0 = __expf(m0 - m), w1 = __expf(m1 - m);
    float w2 = __expf(m2 - m), w3 = __expf(m3 - m);
    float inv = 1.0f / (g_ps[rq]*w0 + g_ps[NRQ+rq]*w1 + g_ps[2*NRQ+rq]*w2 + g_ps[3*NRQ+rq]*w3);
    float4 a0 = *reinterpret_cast<const float4*>(&g_mlp[(size_t)rq*HD + d4*4]);
    float4 a1 = *reinterpret_cast<const float4*>(&g_mlp[(size_t)(NRQ + rq)*HD + d4*4]);
    float4 a2 = *reinterpret_cast<const float4*>(&g_mlp[(size_t)(2*NRQ + rq)*HD + d4*4]);
    float4 a3 = *reinterpret_cast<const float4*>(&g_mlp[(size_t)(3*NRQ + rq)*HD + d4*4]);
    float4 o;
    o.x = (a0.x*w0 + a1.x*w1 + a2.x*w2 + a3.x*w3) * inv;
    o.y = (a0.y*w0 + a1.y*w1 + a2.y*w2 + a3.y*w3) * inv;
    o.z = (a0.z*w0 + a1.z*w1 + a2.z*w2 + a3.z*w3) * inv;
    o.w = (a0.w*w0 + a1.w*w1 + a2.w*w2 + a3.w*w3) * inv;
    *reinterpret_cast<float4*>(&g_y[(size_t)(b*NN + qi)*HID + h*HD + d4*4]) = o;
}

// ---------------- decode: out = 10*tanh((h@Wdec)/sqrt(128)) ----------------
__global__ void k_dec(const float* __restrict__ Wdec, float* __restrict__ out) {
    int r = blockIdx.x * 8 + (threadIdx.x >> 5);
    int lane = threadIdx.x & 31;
    float4 hv = *reinterpret_cast<const float4*>(&g_h[r*HID + lane*4]);
    float4 wv = *reinterpret_cast<const float4*>(&Wdec[lane*4]);
    float s = hv.x*wv.x + hv.y*wv.y + hv.z*wv.z + hv.w*wv.w;
    #pragma unroll
    for (int o = 16; o > 0; o >>= 1) s += __shfl_xor_sync(0xffffffffu, s, o);
    if (lane == 0) out[r] = 10.0f * tanhf(s * 0.08838834764831845f);
}

// ---------------- launch ---------------------------------------------------
extern "C" void kernel_launch(void* const* d_in, const int* in_sizes, int n_in,
                              void* d_out, int out_size) {
    const float* nf    = (const float*)d_in[0];
    const float* edge  = (const float*)d_in[1];
    const float* Wn    = (const float*)d_in[2];
    const float* We_in = (const float*)d_in[3];
    const float* ln1_g = (const float*)d_in[4];
    const float* ln1_b = (const float*)d_in[5];
    const float* Wh    = (const float*)d_in[6];
    const float* We    = (const float*)d_in[7];
    const float* ln2_g = (const float*)d_in[8];
    const float* ln2_b = (const float*)d_in[9];
    const float* W1    = (const float*)d_in[10];
    const float* W2    = (const float*)d_in[11];
    const float* Wdec  = (const float*)d_in[12];
    float* out = (float*)d_out;

    cudaFuncSetAttribute(k_lngemm<0,0>, cudaFuncAttributeMaxDynamicSharedMemorySize, LNG_SMEM);
    cudaFuncSetAttribute(k_lngemm<1,1>, cudaFuncAttributeMaxDynamicSharedMemorySize, LNG_SMEM);

    k_coef<<<1, 64>>>(We_in, We);
    k_embed<<<(ROWS*HID/4)/256, 256>>>(nf, Wn);

    for (int l = 0; l < 3; l++) {
        // qkv = LN1(h) @ Wh[l]   (4096x128 @ 128x384), LN fused
        k_lngemm<0,0><<<dim3(6, 32), 256, LNG_SMEM>>>(
            0, -1, Wh + (size_t)l*HID*384, 2, 384, ln1_g + l*HID, ln1_b + l*HID);
        // attention (split-KV x4, 2 queries/thread) -> partials -> combine -> y
        k_attn<<<NSEG*NBH, 128>>>(edge, l);
        k_attn_comb<<<(NRQ*4)/256, 256>>>();
        // mlp hidden = relu(LN2(y + h) @ W1[l])   (4096x128 @ 128x512), LN fused
        k_lngemm<1,1><<<dim3(8, 32), 256, LNG_SMEM>>>(
            3, 0, W1 + (size_t)l*HID*512, 5, 512, ln2_g + l*HID, ln2_b + l*HID);
        // h = mlp_hidden @ W2[l] + y     (4096x512 @ 512x128), kc=32
        k_gemm2<<<dim3(2, 64), 256>>>(5, W2 + (size_t)l*512*HID, 3, 0, 512, 128);
    }

    k_dec<<<ROWS/8, 256>>>(Wdec, out);
}

// round 15
// speedup vs baseline: 1.0222x; 1.0222x over previous
#include <cuda_runtime.h>
#include <math.h>

#define BB 16
#define NN 256
#define HID 128
#define NHEAD 8
#define HD 16
#define ROWS (BB*NN)   // 4096
#define NBH (BB*NHEAD) // 128
#define NRQ (NBH*NN)   // 32768 (bh, query) pairs
#define NSEG 2         // key-split segments
#define SEGK (NN/NSEG) // 128 keys per segment

typedef unsigned long long u64;

// ---------------- f32x2 packed-FMA helpers (sm_103a dual-issue fp32) -------
__device__ __forceinline__ u64 pack2(float x, float y) {
    u64 r; asm("mov.b64 %0, {%1, %2};" : "=l"(r) : "f"(x), "f"(y)); return r;
}
__device__ __forceinline__ u64 packdup(float x) { return pack2(x, x); }
__device__ __forceinline__ float2 unpack2(u64 p) {
    float2 f; asm("mov.b64 {%0, %1}, %2;" : "=f"(f.x), "=f"(f.y) : "l"(p)); return f;
}
__device__ __forceinline__ u64 ffma2(u64 a, u64 b, u64 c) {
    u64 d; asm("fma.rn.f32x2 %0, %1, %2, %3;" : "=l"(d) : "l"(a), "l"(b), "l"(c)); return d;
}
__device__ __forceinline__ u64 fmul2(u64 a, u64 b) {
    u64 d; asm("mul.rn.f32x2 %0, %1, %2;" : "=l"(d) : "l"(a), "l"(b)); return d;
}

// ---------------- scratch (device globals; no allocation allowed) ----------
__device__ float g_h[ROWS*HID];        // layer input / output h
__device__ float g_qkv[ROWS*3*HID];    // qkv
__device__ float g_y[ROWS*HID];        // attention output
__device__ float g_mlp[ROWS*4*HID];    // MLP hidden; also attn partial acc scratch
__device__ float g_pm[NSEG*NRQ];       // attn partial max
__device__ float g_ps[NSEG*NRQ];       // attn partial sum
__device__ float g_c1[3*NHEAD];
__device__ float g_c2[3*NHEAD];

__device__ __forceinline__ float* bufptr(int id) {
    switch (id) {
        case 0: return g_h;
        case 2: return g_qkv;
        case 3: return g_y;
        default: return g_mlp;
    }
}

// ---------------- edge coefficient precompute ------------------------------
__global__ void k_coef(const float* __restrict__ We_in, const float* __restrict__ We) {
    int t = threadIdx.x;
    if (t >= 48) return;
    int l = t / 16, c = t % 16;
    float s = 0.f;
    for (int d = 0; d < HID; d++) s += We_in[d] * We[(l*HID + d)*16 + c];
    if (c < NHEAD) g_c1[l*NHEAD + c] = s;
    else           g_c2[l*NHEAD + (c - NHEAD)] = s;
}

// ---------------- node embedding: h = nf @ Wn (K=2), float4 ----------------
__global__ void k_embed(const float* __restrict__ nf, const float* __restrict__ Wn) {
    int i = blockIdx.x * blockDim.x + threadIdx.x;   // one float4 per thread
    int r = i >> 5, c4 = (i & 31) * 4;
    float a = nf[r*2], b = nf[r*2+1];
    float4 w0 = *reinterpret_cast<const float4*>(&Wn[c4]);
    float4 w1 = *reinterpret_cast<const float4*>(&Wn[HID + c4]);
    float4 o;
    o.x = a*w0.x + b*w1.x; o.y = a*w0.y + b*w1.y;
    o.z = a*w0.z + b*w1.z; o.w = a*w0.w + b*w1.w;
    *reinterpret_cast<float4*>(&g_h[r*HID + c4]) = o;
}

// ---------------- fused LN + GEMM (K = HID = 128 only), f32x2 core ---------
// C[128 x 64 tile] = LN(X [+ R]) @ W.   RELU optionally applied.
#define AS_STRIDE 132
#define LNG_SMEM ((128*AS_STRIDE + 128*64) * 4)

template<int RES, int RELU>
__global__ __launch_bounds__(256)
void k_lngemm(int xid, int resid, const float* __restrict__ Bm, int cid, int Nc,
              const float* __restrict__ gam, const float* __restrict__ bet) {
    extern __shared__ __align__(16) float sm[];
    float* As = sm;                    // [128][AS_STRIDE]
    float* Bs = sm + 128*AS_STRIDE;    // [128][64]
    const float* X = bufptr(xid);
    const float* Rp = RES ? bufptr(resid) : nullptr;
    float* C = bufptr(cid);
    int tid = threadIdx.x, lane = tid & 31, warp = tid >> 5;
    int rowBase = blockIdx.y * 128, colBase = blockIdx.x * 64;

    // ---- stage B panel: 128 x 64, coalesced ----
    #pragma unroll
    for (int i = 0; i < 8; i++) {
        int f4 = i*256 + tid;
        int kk = f4 >> 4, n = (f4 & 15) * 4;
        *reinterpret_cast<float4*>(&Bs[kk*64 + n]) =
            *reinterpret_cast<const float4*>(&Bm[(size_t)kk*Nc + colBase + n]);
    }

    // ---- stage A panel with fused layernorm: one warp per row ----
    float4 gv = *reinterpret_cast<const float4*>(&gam[lane*4]);
    float4 bv = *reinterpret_cast<const float4*>(&bet[lane*4]);
    #pragma unroll
    for (int i = 0; i < 16; i++) {
        int r = i*8 + warp;
        float4 v = *reinterpret_cast<const float4*>(
            &X[(size_t)(rowBase + r)*HID + lane*4]);
        if (RES) {
            float4 rv = *reinterpret_cast<const float4*>(
                &Rp[(size_t)(rowBase + r)*HID + lane*4]);
            v.x += rv.x; v.y += rv.y; v.z += rv.z; v.w += rv.w;
        }
        float s = v.x + v.y + v.z + v.w;
        #pragma unroll
        for (int o = 16; o > 0; o >>= 1) s += __shfl_xor_sync(0xffffffffu, s, o);
        float mean = s * (1.0f/HID);
        float dx = v.x-mean, dy = v.y-mean, dz = v.z-mean, dw = v.w-mean;
        float s2 = dx*dx + dy*dy + dz*dz + dw*dw;
        #pragma unroll
        for (int o = 16; o > 0; o >>= 1) s2 += __shfl_xor_sync(0xffffffffu, s2, o);
        float rstd = rsqrtf(s2 * (1.0f/HID) + 1e-5f);
        float4 o4;
        o4.x = dx*rstd*gv.x + bv.x; o4.y = dy*rstd*gv.y + bv.y;
        o4.z = dz*rstd*gv.z + bv.z; o4.w = dw*rstd*gv.w + bv.w;
        *reinterpret_cast<float4*>(&As[r*AS_STRIDE + lane*4]) = o4;
    }
    __syncthreads();

    // ---- compute: per-thread 8x4, K=128, f32x2 packed FMA ----
    int tx = tid & 15, ty = tid >> 4;
    u64 acc2[8][2] = {};
    #pragma unroll 4
    for (int k4 = 0; k4 < 32; k4++) {
        u64 b2[4][2];
        #pragma unroll
        for (int dk = 0; dk < 4; dk++) {
            ulonglong2 t = *reinterpret_cast<ulonglong2*>(&Bs[(k4*4 + dk)*64 + tx*4]);
            b2[dk][0] = t.x; b2[dk][1] = t.y;
        }
        #pragma unroll
        for (int r = 0; r < 8; r++) {
            float4 a4 = *reinterpret_cast<float4*>(&As[(ty*8 + r)*AS_STRIDE + k4*4]);
            u64 ax = packdup(a4.x), ay = packdup(a4.y);
            u64 az = packdup(a4.z), aw = packdup(a4.w);
            acc2[r][0] = ffma2(ax, b2[0][0], acc2[r][0]);
            acc2[r][1] = ffma2(ax, b2[0][1], acc2[r][1]);
            acc2[r][0] = ffma2(ay, b2[1][0], acc2[r][0]);
            acc2[r][1] = ffma2(ay, b2[1][1], acc2[r][1]);
            acc2[r][0] = ffma2(az, b2[2][0], acc2[r][0]);
            acc2[r][1] = ffma2(az, b2[2][1], acc2[r][1]);
            acc2[r][0] = ffma2(aw, b2[3][0], acc2[r][0]);
            acc2[r][1] = ffma2(aw, b2[3][1], acc2[r][1]);
        }
    }
    #pragma unroll
    for (int r = 0; r < 8; r++) {
        int row = rowBase + ty*8 + r;
        int col = colBase + tx*4;
        float2 p0 = unpack2(acc2[r][0]);
        float2 p1 = unpack2(acc2[r][1]);
        float4 v = {p0.x, p0.y, p1.x, p1.y};
        if (RELU) {
            v.x = fmaxf(v.x, 0.f); v.y = fmaxf(v.y, 0.f);
            v.z = fmaxf(v.z, 0.f); v.w = fmaxf(v.w, 0.f);
        }
        *reinterpret_cast<float4*>(&C[(size_t)row*Nc + col]) = v;
    }
}

// ---------------- fp32 GEMM (K=512): C = A @ W + residual, f32x2 core ------
__global__ __launch_bounds__(256)
void k_gemm2(int aid, const float* __restrict__ Bm,
             int resid, int cid, int K, int Nc) {
    __shared__ __align__(16) float As[32][64];
    __shared__ __align__(16) float Bs[32][64];
    const float* A = bufptr(aid);
    float* C = bufptr(cid);
    int tid = threadIdx.x;
    int tx = tid & 15, ty = tid >> 4;
    int rowBase = blockIdx.y * 64;
    int colBase = blockIdx.x * 64;
    u64 acc2[4][2] = {};
    for (int k0 = 0; k0 < K; k0 += 32) {
        #pragma unroll
        for (int q = 0; q < 2; q++) {      // A tile 64m x 32k, transposed store
            int fidx = tid*2 + q;
            int m = fidx >> 3, kk = (fidx & 7) * 4;
            float4 a4 = *reinterpret_cast<const float4*>(&A[(size_t)(rowBase+m)*K + k0 + kk]);
            As[kk+0][m] = a4.x; As[kk+1][m] = a4.y; As[kk+2][m] = a4.z; As[kk+3][m] = a4.w;
        }
        #pragma unroll
        for (int q = 0; q < 2; q++) {      // B tile 32k x 64n, coalesced
            int f4 = q*256 + tid;
            int kk = f4 >> 4, n = (f4 & 15) * 4;
            *reinterpret_cast<float4*>(&Bs[kk][n]) =
                *reinterpret_cast<const float4*>(&Bm[(size_t)(k0+kk)*Nc + colBase + n]);
        }
        __syncthreads();
        #pragma unroll
        for (int kk = 0; kk < 32; kk++) {
            ulonglong2 bb = *reinterpret_cast<ulonglong2*>(&Bs[kk][tx*4]);
            float4 a4 = *reinterpret_cast<float4*>(&As[kk][ty*4]);
            u64 a0 = packdup(a4.x), a1 = packdup(a4.y);
            u64 a2 = packdup(a4.z), a3 = packdup(a4.w);
            acc2[0][0] = ffma2(a0, bb.x, acc2[0][0]);
            acc2[0][1] = ffma2(a0, bb.y, acc2[0][1]);
            acc2[1][0] = ffma2(a1, bb.x, acc2[1][0]);
            acc2[1][1] = ffma2(a1, bb.y, acc2[1][1]);
            acc2[2][0] = ffma2(a2, bb.x, acc2[2][0]);
            acc2[2][1] = ffma2(a2, bb.y, acc2[2][1]);
            acc2[3][0] = ffma2(a3, bb.x, acc2[3][0]);
            acc2[3][1] = ffma2(a3, bb.y, acc2[3][1]);
        }
        __syncthreads();
    }
    const float* R = bufptr(resid);
    #pragma unroll
    for (int i = 0; i < 4; i++) {
        int row = rowBase + ty*4 + i;
        int col = colBase + tx*4;
        float2 p0 = unpack2(acc2[i][0]);
        float2 p1 = unpack2(acc2[i][1]);
        float4 v = {p0.x, p0.y, p1.x, p1.y};
        float4 rv = *reinterpret_cast<const float4*>(&R[(size_t)row*HID + col]);
        v.x += rv.x; v.y += rv.y; v.z += rv.z; v.w += rv.w;
        *reinterpret_cast<float4*>(&C[(size_t)row*Nc + col]) = v;
    }
}

// ---------------- attention, split-KV x2, f32x2 core -----------------------
// Block sg handles keys j in [sg*128, sg*128+128); writes softmax partials.
__global__ __launch_bounds__(256)
void k_attn(const float* __restrict__ edge, int layer) {
    int blk = blockIdx.x;              // 0..255
    int bh = blk & (NBH-1), sg = blk >> 7;
    int b = bh >> 3, h = bh & 7;
    __shared__ __align__(16) float ks[SEGK][HD];
    __shared__ __align__(16) float vs[SEGK][HD];
    int tid = threadIdx.x;             // one query row per thread
    int j0 = sg * SEGK;

    {   // cooperative K/V stage: 128 rows x 4 float4-parts = 512 f4, 2 per thread
        #pragma unroll
        for (int i = 0; i < 2; i++) {
            int idx = i*256 + tid;
            int rr = idx >> 2, part = idx & 3;
            const float* base = &g_qkv[(size_t)(b*NN + j0 + rr)*384 + h*HD];
            *reinterpret_cast<float4*>(&ks[rr][part*4]) =
                *reinterpret_cast<const float4*>(base + HID   + part*4);
            *reinterpret_cast<float4*>(&vs[rr][part*4]) =
                *reinterpret_cast<const float4*>(base + 2*HID + part*4);
        }
    }
    __syncthreads();

    u64 q2[8];                          // packed q pairs (scaled by 1/4)
    {
        const float* qp = &g_qkv[(size_t)(b*NN + tid)*384 + h*HD];
        #pragma unroll
        for (int d4 = 0; d4 < 4; d4++) {
            float4 q4 = *reinterpret_cast<const float4*>(qp + d4*4);
            q2[d4*2+0] = pack2(q4.x*0.25f, q4.y*0.25f);
            q2[d4*2+1] = pack2(q4.z*0.25f, q4.w*0.25f);
        }
    }

    float cb = g_c1[layer*NHEAD + h];
    float cg = g_c2[layer*NHEAD + h];
    const float4* erow4 = reinterpret_cast<const float4*>(edge + (size_t)(b*NN + tid)*NN);

    float mx = -1e30f, sum = 0.f;
    u64 acc2[8] = {};
    #pragma unroll 2
    for (int j4 = 0; j4 < 32; j4++) {
        float4 e4 = __ldg(&erow4[sg*32 + j4]);
        float ejs[4] = {e4.x, e4.y, e4.z, e4.w};
        #pragma unroll
        for (int jj = 0; jj < 4; jj++) {
            int j = j4*4 + jj;          // local key index
            u64 sp = 0;
            #pragma unroll
            for (int p = 0; p < 4; p++) {
                ulonglong2 k2 = *reinterpret_cast<ulonglong2*>(&ks[j][p*4]);
                sp = ffma2(q2[p*2+0], k2.x, sp);
                sp = ffma2(q2[p*2+1], k2.y, sp);
            }
            float2 sf = unpack2(sp);
            float ej = ejs[jj];
            float s = sf.x + sf.y + ej * cb;
            if (s > mx) {
                float sc = __expf(mx - s);
                mx = s; sum *= sc;
                u64 sc2 = packdup(sc);
                #pragma unroll
                for (int d = 0; d < 8; d++) acc2[d] = fmul2(acc2[d], sc2);
            }
            float p = __expf(s - mx);
            sum += p;
            u64 w2 = packdup(p * ej * cg);
            #pragma unroll
            for (int d = 0; d < 4; d++) {
                ulonglong2 v2 = *reinterpret_cast<ulonglong2*>(&vs[j][d*4]);
                acc2[d*2+0] = ffma2(w2, v2.x, acc2[d*2+0]);
                acc2[d*2+1] = ffma2(w2, v2.y, acc2[d*2+1]);
            }
        }
    }
    // write partials (unnormalized; pairs map to consecutive dims)
    int rq = bh*NN + tid;
    g_pm[sg*NRQ + rq] = mx;
    g_ps[sg*NRQ + rq] = sum;
    float* pa = &g_mlp[(size_t)(sg*NRQ + rq)*HD];
    #pragma unroll
    for (int d = 0; d < 4; d++) {
        ulonglong2 t = {acc2[d*2+0], acc2[d*2+1]};
        *reinterpret_cast<ulonglong2*>(pa + d*4) = t;
    }
}

// ---------------- attention combine: merge 2 split-KV partials -------------
__global__ __launch_bounds__(256)
void k_attn_comb() {
    int gid = blockIdx.x * 256 + threadIdx.x;   // 131072 threads
    int rq = gid >> 2, d4 = gid & 3;
    int bh = rq >> 8, qi = rq & 255;
    int b = bh >> 3, h = bh & 7;
    float m0 = g_pm[rq],       s0 = g_ps[rq];
    float m1 = g_pm[NRQ + rq], s1 = g_ps[NRQ + rq];
    float m = fmaxf(m0, m1);
    float w0 = __expf(m0 - m), w1 = __expf(m1 - m);
    float inv = 1.0f / (s0*w0 + s1*w1);
    float4 a0 = *reinterpret_cast<const float4*>(&g_mlp[(size_t)rq*HD + d4*4]);
    float4 a1 = *reinterpret_cast<const float4*>(&g_mlp[(size_t)(NRQ + rq)*HD + d4*4]);
    float4 o;
    o.x = (a0.x*w0 + a1.x*w1) * inv;
    o.y = (a0.y*w0 + a1.y*w1) * inv;
    o.z = (a0.z*w0 + a1.z*w1) * inv;
    o.w = (a0.w*w0 + a1.w*w1) * inv;
    *reinterpret_cast<float4*>(&g_y[(size_t)(b*NN + qi)*HID + h*HD + d4*4]) = o;
}

// ---------------- decode: out = 10*tanh((h@Wdec)/sqrt(128)) ----------------
__global__ void k_dec(const float* __restrict__ Wdec, float* __restrict__ out) {
    int r = blockIdx.x * 8 + (threadIdx.x >> 5);
    int lane = threadIdx.x & 31;
    float4 hv = *reinterpret_cast<const float4*>(&g_h[r*HID + lane*4]);
    float4 wv = *reinterpret_cast<const float4*>(&Wdec[lane*4]);
    float s = hv.x*wv.x + hv.y*wv.y + hv.z*wv.z + hv.w*wv.w;
    #pragma unroll
    for (int o = 16; o > 0; o >>= 1) s += __shfl_xor_sync(0xffffffffu, s, o);
    if (lane == 0) out[r] = 10.0f * tanhf(s * 0.08838834764831845f);
}

// ---------------- launch ---------------------------------------------------
extern "C" void kernel_launch(void* const* d_in, const int* in_sizes, int n_in,
                              void* d_out, int out_size) {
    const float* nf    = (const float*)d_in[0];
    const float* edge  = (const float*)d_in[1];
    const float* Wn    = (const float*)d_in[2];
    const float* We_in = (const float*)d_in[3];
    const float* ln1_g = (const float*)d_in[4];
    const float* ln1_b = (const float*)d_in[5];
    const float* Wh    = (const float*)d_in[6];
    const float* We    = (const float*)d_in[7];
    const float* ln2_g = (const float*)d_in[8];
    const float* ln2_b = (const float*)d_in[9];
    const float* W1    = (const float*)d_in[10];
    const float* W2    = (const float*)d_in[11];
    const float* Wdec  = (const float*)d_in[12];
    float* out = (float*)d_out;

    cudaFuncSetAttribute(k_lngemm<0,0>, cudaFuncAttributeMaxDynamicSharedMemorySize, LNG_SMEM);
    cudaFuncSetAttribute(k_lngemm<1,1>, cudaFuncAttributeMaxDynamicSharedMemorySize, LNG_SMEM);

    k_coef<<<1, 64>>>(We_in, We);
    k_embed<<<(ROWS*HID/4)/256, 256>>>(nf, Wn);

    for (int l = 0; l < 3; l++) {
        // qkv = LN1(h) @ Wh[l]   (4096x128 @ 128x384), LN fused, f32x2
        k_lngemm<0,0><<<dim3(6, 32), 256, LNG_SMEM>>>(
            0, -1, Wh + (size_t)l*HID*384, 2, 384, ln1_g + l*HID, ln1_b + l*HID);
        // attention (split-KV x2) -> partials -> combine -> y
        k_attn<<<NSEG*NBH, 256>>>(edge, l);
        k_attn_comb<<<(NRQ*4)/256, 256>>>();
        // mlp hidden = relu(LN2(y + h) @ W1[l])   (4096x128 @ 128x512), LN fused, f32x2
        k_lngemm<1,1><<<dim3(8, 32), 256, LNG_SMEM>>>(
            3, 0, W1 + (size_t)l*HID*512, 5, 512, ln2_g + l*HID, ln2_b + l*HID);
        // h = mlp_hidden @ W2[l] + y     (4096x512 @ 512x128), f32x2
        k_gemm2<<<dim3(2, 64), 256>>>(5, W2 + (size_t)l*512*HID, 3, 0, 512, 128);
    }

    k_dec<<<ROWS/8, 256>>>(Wdec, out);
}

// round 17
// speedup vs baseline: 1.1216x; 1.0973x over previous
#include <cuda_runtime.h>
#include <math.h>

#define BB 16
#define NN 256
#define HID 128
#define NHEAD 8
#define HD 16
#define ROWS (BB*NN)   // 4096
#define NBH (BB*NHEAD) // 128
#define NRQ (NBH*NN)   // 32768 (bh, query) pairs
#define NSEG 2         // key-split segments
#define SEGK (NN/NSEG) // 128 keys per segment

typedef unsigned long long u64;

// ---------------- f32x2 packed-FMA helpers (sm_103a dual-issue fp32) -------
__device__ __forceinline__ u64 pack2(float x, float y) {
    u64 r; asm("mov.b64 %0, {%1, %2};" : "=l"(r) : "f"(x), "f"(y)); return r;
}
__device__ __forceinline__ u64 packdup(float x) { return pack2(x, x); }
__device__ __forceinline__ float2 unpack2(u64 p) {
    float2 f; asm("mov.b64 {%0, %1}, %2;" : "=f"(f.x), "=f"(f.y) : "l"(p)); return f;
}
__device__ __forceinline__ u64 ffma2(u64 a, u64 b, u64 c) {
    u64 d; asm("fma.rn.f32x2 %0, %1, %2, %3;" : "=l"(d) : "l"(a), "l"(b), "l"(c)); return d;
}
__device__ __forceinline__ u64 fmul2(u64 a, u64 b) {
    u64 d; asm("mul.rn.f32x2 %0, %1, %2;" : "=l"(d) : "l"(a), "l"(b)); return d;
}

// ---------------- scratch (device globals; no allocation allowed) ----------
__device__ float g_h[ROWS*HID];        // layer input / output h
__device__ float g_qkv[ROWS*3*HID];    // qkv
__device__ float g_y[ROWS*HID];        // attention output
__device__ float g_mlp[ROWS*4*HID];    // MLP hidden; also attn partial acc scratch
__device__ float g_gp[2*ROWS*HID];     // gemm2 split-K partials
__device__ float g_pm[NSEG*NRQ];       // attn partial max
__device__ float g_ps[NSEG*NRQ];       // attn partial sum
__device__ float g_c1[3*NHEAD];
__device__ float g_c2[3*NHEAD];

__device__ __forceinline__ float* bufptr(int id) {
    switch (id) {
        case 0: return g_h;
        case 2: return g_qkv;
        case 3: return g_y;
        default: return g_mlp;
    }
}

// ---------------- edge coefficient precompute ------------------------------
__global__ void k_coef(const float* __restrict__ We_in, const float* __restrict__ We) {
    int t = threadIdx.x;
    if (t >= 48) return;
    int l = t / 16, c = t % 16;
    float s = 0.f;
    for (int d = 0; d < HID; d++) s += We_in[d] * We[(l*HID + d)*16 + c];
    if (c < NHEAD) g_c1[l*NHEAD + c] = s;
    else           g_c2[l*NHEAD + (c - NHEAD)] = s;
}

// ---------------- node embedding: h = nf @ Wn (K=2), float4 ----------------
__global__ void k_embed(const float* __restrict__ nf, const float* __restrict__ Wn) {
    int i = blockIdx.x * blockDim.x + threadIdx.x;   // one float4 per thread
    int r = i >> 5, c4 = (i & 31) * 4;
    float a = nf[r*2], b = nf[r*2+1];
    float4 w0 = *reinterpret_cast<const float4*>(&Wn[c4]);
    float4 w1 = *reinterpret_cast<const float4*>(&Wn[HID + c4]);
    float4 o;
    o.x = a*w0.x + b*w1.x; o.y = a*w0.y + b*w1.y;
    o.z = a*w0.z + b*w1.z; o.w = a*w0.w + b*w1.w;
    *reinterpret_cast<float4*>(&g_h[r*HID + c4]) = o;
}

// ---------------- fused LN + GEMM (K = HID = 128), 64x64 tile, f32x2 -------
// C[64 x 64 tile] = LN(X [+ R]) @ W.   A panel is 64 rows x 128 (full K).
#define LNG_SMEM ((64*128 + 128*64) * 4)   // 64KB

template<int RES, int RELU>
__global__ __launch_bounds__(256)
void k_lngemm(int xid, int resid, const float* __restrict__ Bm, int cid, int Nc,
              const float* __restrict__ gam, const float* __restrict__ bet) {
    extern __shared__ __align__(16) float sm[];
    float* As = sm;                    // [64][128]  (row-major, full K)
    float* Bs = sm + 64*128;           // [128][64]
    const float* X = bufptr(xid);
    const float* Rp = RES ? bufptr(resid) : nullptr;
    float* C = bufptr(cid);
    int tid = threadIdx.x, lane = tid & 31, warp = tid >> 5;
    int rowBase = blockIdx.y * 64, colBase = blockIdx.x * 64;

    // ---- stage B panel: 128 x 64, coalesced (8 float4 per thread) ----
    #pragma unroll
    for (int i = 0; i < 8; i++) {
        int f4 = i*256 + tid;
        int kk = f4 >> 4, n = (f4 & 15) * 4;
        *reinterpret_cast<float4*>(&Bs[kk*64 + n]) =
            *reinterpret_cast<const float4*>(&Bm[(size_t)kk*Nc + colBase + n]);
    }

    // ---- stage A panel with fused layernorm: one warp per row, 8 iters ----
    float4 gv = *reinterpret_cast<const float4*>(&gam[lane*4]);
    float4 bv = *reinterpret_cast<const float4*>(&bet[lane*4]);
    #pragma unroll
    for (int i = 0; i < 8; i++) {
        int r = i*8 + warp;
        float4 v = *reinterpret_cast<const float4*>(
            &X[(size_t)(rowBase + r)*HID + lane*4]);
        if (RES) {
            float4 rv = *reinterpret_cast<const float4*>(
                &Rp[(size_t)(rowBase + r)*HID + lane*4]);
            v.x += rv.x; v.y += rv.y; v.z += rv.z; v.w += rv.w;
        }
        float s = v.x + v.y + v.z + v.w;
        #pragma unroll
        for (int o = 16; o > 0; o >>= 1) s += __shfl_xor_sync(0xffffffffu, s, o);
        float mean = s * (1.0f/HID);
        float dx = v.x-mean, dy = v.y-mean, dz = v.z-mean, dw = v.w-mean;
        float s2 = dx*dx + dy*dy + dz*dz + dw*dw;
        #pragma unroll
        for (int o = 16; o > 0; o >>= 1) s2 += __shfl_xor_sync(0xffffffffu, s2, o);
        float rstd = rsqrtf(s2 * (1.0f/HID) + 1e-5f);
        float4 o4;
        o4.x = dx*rstd*gv.x + bv.x; o4.y = dy*rstd*gv.y + bv.y;
        o4.z = dz*rstd*gv.z + bv.z; o4.w = dw*rstd*gv.w + bv.w;
        *reinterpret_cast<float4*>(&As[r*128 + lane*4]) = o4;   // conflict-free STS.128
    }
    __syncthreads();

    // ---- compute: per-thread 4x4, K=128, f32x2 packed FMA ----
    int tx = tid & 15, ty = tid >> 4;
    u64 acc2[4][2] = {};
    #pragma unroll 4
    for (int k4 = 0; k4 < 32; k4++) {
        u64 b2[4][2];
        #pragma unroll
        for (int dk = 0; dk < 4; dk++) {
            ulonglong2 t = *reinterpret_cast<ulonglong2*>(&Bs[(k4*4 + dk)*64 + tx*4]);
            b2[dk][0] = t.x; b2[dk][1] = t.y;
        }
        #pragma unroll
        for (int r = 0; r < 4; r++) {
            float4 a4 = *reinterpret_cast<float4*>(&As[(ty*4 + r)*128 + k4*4]);
            u64 ax = packdup(a4.x), ay = packdup(a4.y);
            u64 az = packdup(a4.z), aw = packdup(a4.w);
            acc2[r][0] = ffma2(ax, b2[0][0], acc2[r][0]);
            acc2[r][1] = ffma2(ax, b2[0][1], acc2[r][1]);
            acc2[r][0] = ffma2(ay, b2[1][0], acc2[r][0]);
            acc2[r][1] = ffma2(ay, b2[1][1], acc2[r][1]);
            acc2[r][0] = ffma2(az, b2[2][0], acc2[r][0]);
            acc2[r][1] = ffma2(az, b2[2][1], acc2[r][1]);
            acc2[r][0] = ffma2(aw, b2[3][0], acc2[r][0]);
            acc2[r][1] = ffma2(aw, b2[3][1], acc2[r][1]);
        }
    }
    #pragma unroll
    for (int r = 0; r < 4; r++) {
        int row = rowBase + ty*4 + r;
        int col = colBase + tx*4;
        float2 p0 = unpack2(acc2[r][0]);
        float2 p1 = unpack2(acc2[r][1]);
        float4 v = {p0.x, p0.y, p1.x, p1.y};
        if (RELU) {
            v.x = fmaxf(v.x, 0.f); v.y = fmaxf(v.y, 0.f);
            v.z = fmaxf(v.z, 0.f); v.w = fmaxf(v.w, 0.f);
        }
        *reinterpret_cast<float4*>(&C[(size_t)row*Nc + col]) = v;
    }
}

// ---------------- gemm2 split-K: partial = A[.,kz] @ W[kz,.], f32x2 --------
// blockIdx.z selects K half [z*256, z*256+256). Writes g_gp partials.
__global__ __launch_bounds__(256)
void k_gemm2(const float* __restrict__ Bm) {
    __shared__ __align__(16) float As[32][64];
    __shared__ __align__(16) float Bs[32][64];
    const float* A = g_mlp;
    int tid = threadIdx.x;
    int tx = tid & 15, ty = tid >> 4;
    int rowBase = blockIdx.y * 64;
    int colBase = blockIdx.x * 64;
    int z = blockIdx.z;
    u64 acc2[4][2] = {};
    for (int k0 = z*256; k0 < z*256 + 256; k0 += 32) {
        #pragma unroll
        for (int q = 0; q < 2; q++) {      // A tile 64m x 32k, transposed store
            int fidx = tid*2 + q;
            int m = fidx >> 3, kk = (fidx & 7) * 4;
            float4 a4 = *reinterpret_cast<const float4*>(&A[(size_t)(rowBase+m)*512 + k0 + kk]);
            As[kk+0][m] = a4.x; As[kk+1][m] = a4.y; As[kk+2][m] = a4.z; As[kk+3][m] = a4.w;
        }
        #pragma unroll
        for (int q = 0; q < 2; q++) {      // B tile 32k x 64n, coalesced
            int f4 = q*256 + tid;
            int kk = f4 >> 4, n = (f4 & 15) * 4;
            *reinterpret_cast<float4*>(&Bs[kk][n]) =
                *reinterpret_cast<const float4*>(&Bm[(size_t)(k0+kk)*HID + colBase + n]);
        }
        __syncthreads();
        #pragma unroll
        for (int kk = 0; kk < 32; kk++) {
            ulonglong2 bb = *reinterpret_cast<ulonglong2*>(&Bs[kk][tx*4]);
            float4 a4 = *reinterpret_cast<float4*>(&As[kk][ty*4]);
            u64 a0 = packdup(a4.x), a1 = packdup(a4.y);
            u64 a2 = packdup(a4.z), a3 = packdup(a4.w);
            acc2[0][0] = ffma2(a0, bb.x, acc2[0][0]);
            acc2[0][1] = ffma2(a0, bb.y, acc2[0][1]);
            acc2[1][0] = ffma2(a1, bb.x, acc2[1][0]);
            acc2[1][1] = ffma2(a1, bb.y, acc2[1][1]);
            acc2[2][0] = ffma2(a2, bb.x, acc2[2][0]);
            acc2[2][1] = ffma2(a2, bb.y, acc2[2][1]);
            acc2[3][0] = ffma2(a3, bb.x, acc2[3][0]);
            acc2[3][1] = ffma2(a3, bb.y, acc2[3][1]);
        }
        __syncthreads();
    }
    float* P = g_gp + (size_t)z*ROWS*HID;
    #pragma unroll
    for (int i = 0; i < 4; i++) {
        int row = rowBase + ty*4 + i;
        int col = colBase + tx*4;
        float2 p0 = unpack2(acc2[i][0]);
        float2 p1 = unpack2(acc2[i][1]);
        float4 v = {p0.x, p0.y, p1.x, p1.y};
        *reinterpret_cast<float4*>(&P[(size_t)row*HID + col]) = v;
    }
}

// ---------------- gemm2 combine: h = gp0 + gp1 + y (deterministic) ---------
__global__ __launch_bounds__(256)
void k_g2comb() {
    int gid = blockIdx.x * 256 + threadIdx.x;   // ROWS*HID/4 threads
    float4 a = *reinterpret_cast<const float4*>(&g_gp[(size_t)gid*4]);
    float4 b = *reinterpret_cast<const float4*>(&g_gp[(size_t)ROWS*HID + gid*4]);
    float4 y = *reinterpret_cast<const float4*>(&g_y[(size_t)gid*4]);
    float4 o = {a.x + b.x + y.x, a.y + b.y + y.y,
                a.z + b.z + y.z, a.w + b.w + y.w};
    *reinterpret_cast<float4*>(&g_h[(size_t)gid*4]) = o;
}

// ---------------- attention, split-KV x2, chunked branchless softmax -------
// Block sg handles keys j in [sg*128, sg*128+128); 8-key chunks, one
// unconditional rescale per chunk. Writes unnormalized softmax partials.
__global__ __launch_bounds__(256)
void k_attn(const float* __restrict__ edge, int layer) {
    int blk = blockIdx.x;              // 0..255
    int bh = blk & (NBH-1), sg = blk >> 7;
    int b = bh >> 3, h = bh & 7;
    __shared__ __align__(16) float ks[SEGK][HD];
    __shared__ __align__(16) float vs[SEGK][HD];
    int tid = threadIdx.x;             // one query row per thread
    int j0 = sg * SEGK;

    {   // cooperative K/V stage
        #pragma unroll
        for (int i = 0; i < 2; i++) {
            int idx = i*256 + tid;
            int rr = idx >> 2, part = idx & 3;
            const float* base = &g_qkv[(size_t)(b*NN + j0 + rr)*384 + h*HD];
            *reinterpret_cast<float4*>(&ks[rr][part*4]) =
                *reinterpret_cast<const float4*>(base + HID   + part*4);
            *reinterpret_cast<float4*>(&vs[rr][part*4]) =
                *reinterpret_cast<const float4*>(base + 2*HID + part*4);
        }
    }
    __syncthreads();

    u64 q2[8];                          // packed q pairs (scaled by 1/4)
    {
        const float* qp = &g_qkv[(size_t)(b*NN + tid)*384 + h*HD];
        #pragma unroll
        for (int d4 = 0; d4 < 4; d4++) {
            float4 q4 = *reinterpret_cast<const float4*>(qp + d4*4);
            q2[d4*2+0] = pack2(q4.x*0.25f, q4.y*0.25f);
            q2[d4*2+1] = pack2(q4.z*0.25f, q4.w*0.25f);
        }
    }

    float cb = g_c1[layer*NHEAD + h];
    float cg = g_c2[layer*NHEAD + h];
    const float4* erow4 = reinterpret_cast<const float4*>(edge + (size_t)(b*NN + tid)*NN);

    float mx = -1e30f, sum = 0.f;
    u64 acc2[8] = {};
    #pragma unroll 1
    for (int ch = 0; ch < SEGK/8; ch++) {       // 16 chunks of 8 keys
        float4 e4a = __ldg(&erow4[sg*32 + ch*2]);
        float4 e4b = __ldg(&erow4[sg*32 + ch*2 + 1]);
        float ej[8] = {e4a.x, e4a.y, e4a.z, e4a.w, e4b.x, e4b.y, e4b.z, e4b.w};
        float sc[8];
        #pragma unroll
        for (int c = 0; c < 8; c++) {
            int j = ch*8 + c;
            u64 sp = 0;
            #pragma unroll
            for (int p = 0; p < 4; p++) {
                ulonglong2 k2 = *reinterpret_cast<ulonglong2*>(&ks[j][p*4]);
                sp = ffma2(q2[p*2+0], k2.x, sp);
                sp = ffma2(q2[p*2+1], k2.y, sp);
            }
            float2 sf = unpack2(sp);
            sc[c] = sf.x + sf.y + ej[c] * cb;
        }
        // chunk max + single unconditional rescale (branch-free)
        float cm = sc[0];
        #pragma unroll
        for (int c = 1; c < 8; c++) cm = fmaxf(cm, sc[c]);
        float mnew = fmaxf(mx, cm);
        float scale = __expf(mx - mnew);        // == 1 when max unchanged
        mx = mnew;
        sum *= scale;
        u64 s2 = packdup(scale);
        #pragma unroll
        for (int d = 0; d < 8; d++) acc2[d] = fmul2(acc2[d], s2);
        // branch-free accumulate
        #pragma unroll
        for (int c = 0; c < 8; c++) {
            int j = ch*8 + c;
            float p = __expf(sc[c] - mx);
            sum += p;
            u64 w2 = packdup(p * ej[c] * cg);
            #pragma unroll
            for (int d = 0; d < 4; d++) {
                ulonglong2 v2 = *reinterpret_cast<ulonglong2*>(&vs[j][d*4]);
                acc2[d*2+0] = ffma2(w2, v2.x, acc2[d*2+0]);
                acc2[d*2+1] = ffma2(w2, v2.y, acc2[d*2+1]);
            }
        }
    }
    // write partials (unnormalized)
    int rq = bh*NN + tid;
    g_pm[sg*NRQ + rq] = mx;
    g_ps[sg*NRQ + rq] = sum;
    float* pa = &g_mlp[(size_t)(sg*NRQ + rq)*HD];
    #pragma unroll
    for (int d = 0; d < 4; d++) {
        ulonglong2 t = {acc2[d*2+0], acc2[d*2+1]};
        *reinterpret_cast<ulonglong2*>(pa + d*4) = t;
    }
}

// ---------------- attention combine: merge 2 split-KV partials -------------
__global__ __launch_bounds__(256)
void k_attn_comb() {
    int gid = blockIdx.x * 256 + threadIdx.x;   // 131072 threads
    int rq = gid >> 2, d4 = gid & 3;
    int bh = rq >> 8, qi = rq & 255;
    int b = bh >> 3, h = bh & 7;
    float m0 = g_pm[rq],       s0 = g_ps[rq];
    float m1 = g_pm[NRQ + rq], s1 = g_ps[NRQ + rq];
    float m = fmaxf(m0, m1);
    float w0 = __expf(m0 - m), w1 = __expf(m1 - m);
    float inv = 1.0f / (s0*w0 + s1*w1);
    float4 a0 = *reinterpret_cast<const float4*>(&g_mlp[(size_t)rq*HD + d4*4]);
    float4 a1 = *reinterpret_cast<const float4*>(&g_mlp[(size_t)(NRQ + rq)*HD + d4*4]);
    float4 o;
    o.x = (a0.x*w0 + a1.x*w1) * inv;
    o.y = (a0.y*w0 + a1.y*w1) * inv;
    o.z = (a0.z*w0 + a1.z*w1) * inv;
    o.w = (a0.w*w0 + a1.w*w1) * inv;
    *reinterpret_cast<float4*>(&g_y[(size_t)(b*NN + qi)*HID + h*HD + d4*4]) = o;
}

// ---------------- decode: out = 10*tanh((h@Wdec)/sqrt(128)) ----------------
__global__ void k_dec(const float* __restrict__ Wdec, float* __restrict__ out) {
    int r = blockIdx.x * 8 + (threadIdx.x >> 5);
    int lane = threadIdx.x & 31;
    float4 hv = *reinterpret_cast<const float4*>(&g_h[r*HID + lane*4]);
    float4 wv = *reinterpret_cast<const float4*>(&Wdec[lane*4]);
    float s = hv.x*wv.x + hv.y*wv.y + hv.z*wv.z + hv.w*wv.w;
    #pragma unroll
    for (int o = 16; o > 0; o >>= 1) s += __shfl_xor_sync(0xffffffffu, s, o);
    if (lane == 0) out[r] = 10.0f * tanhf(s * 0.08838834764831845f);
}

// ---------------- launch ---------------------------------------------------
extern "C" void kernel_launch(void* const* d_in, const int* in_sizes, int n_in,
                              void* d_out, int out_size) {
    const float* nf    = (const float*)d_in[0];
    const float* edge  = (const float*)d_in[1];
    const float* Wn    = (const float*)d_in[2];
    const float* We_in = (const float*)d_in[3];
    const float* ln1_g = (const float*)d_in[4];
    const float* ln1_b = (const float*)d_in[5];
    const float* Wh    = (const float*)d_in[6];
    const float* We    = (const float*)d_in[7];
    const float* ln2_g = (const float*)d_in[8];
    const float* ln2_b = (const float*)d_in[9];
    const float* W1    = (const float*)d_in[10];
    const float* W2    = (const float*)d_in[11];
    const float* Wdec  = (const float*)d_in[12];
    float* out = (float*)d_out;

    cudaFuncSetAttribute(k_lngemm<0,0>, cudaFuncAttributeMaxDynamicSharedMemorySize, LNG_SMEM);
    cudaFuncSetAttribute(k_lngemm<1,1>, cudaFuncAttributeMaxDynamicSharedMemorySize, LNG_SMEM);

    k_coef<<<1, 64>>>(We_in, We);
    k_embed<<<(ROWS*HID/4)/256, 256>>>(nf, Wn);

    for (int l = 0; l < 3; l++) {
        // qkv = LN1(h) @ Wh[l]   (4096x128 @ 128x384), LN fused, 64x64 tiles
        k_lngemm<0,0><<<dim3(6, 64), 256, LNG_SMEM>>>(
            0, -1, Wh + (size_t)l*HID*384, 2, 384, ln1_g + l*HID, ln1_b + l*HID);
        // attention (split-KV x2, chunked softmax) -> partials -> combine -> y
        k_attn<<<NSEG*NBH, 256>>>(edge, l);
        k_attn_comb<<<(NRQ*4)/256, 256>>>();
        // mlp hidden = relu(LN2(y + h) @ W1[l])   (4096x128 @ 128x512), LN fused
        k_lngemm<1,1><<<dim3(8, 64), 256, LNG_SMEM>>>(
            3, 0, W1 + (size_t)l*HID*512, 5, 512, ln2_g + l*HID, ln2_b + l*HID);
        // h = mlp_hidden @ W2[l] + y : split-K x2 partials, then combine
        k_gemm2<<<dim3(2, 64, 2), 256>>>(W2 + (size_t)l*512*HID);
        k_g2comb<<<(ROWS*HID/4)/256, 256>>>();
    }

    k_dec<<<ROWS/8, 256>>>(Wdec, out);
}